// round 3
// baseline (speedup 1.0000x reference)
#include <cuda_runtime.h>

// DotAttention: rnn_out [S,B,H] f32, state [2,2,B,H/2] f32 -> out [B,H,1] f32
// S=2048, B=32, H=1024.
// pass1: flash-style online-softmax partials; one warp per (b, 16-row chunk),
//        software-pipelined (double-buffered row loads), merged vector in smem.
// pass2: fused combine (M/L) + weighted sum of partial accumulators.

#define S_LEN 2048
#define B_DIM 32
#define H_DIM 1024
#define SPLIT 128
#define CHUNK (S_LEN / SPLIT)          // 16 rows per warp
#define WARPS_PER_CTA 8
#define NPART (B_DIM * SPLIT)          // 4096 partials

__device__ float g_m[NPART];
__device__ float g_l[NPART];
__device__ float g_acc[(size_t)NPART * H_DIM];   // ~16.8 MB scratch (L2-resident)

__device__ __forceinline__ void process_row(const float4* __restrict__ x,
                                            float4* __restrict__ acc,
                                            float& m, float& l,
                                            const float4* __restrict__ s_mrg,
                                            int lane) {
    float p = 0.f;
#pragma unroll
    for (int j = 0; j < 8; j++) {
        float4 g = s_mrg[j * 32 + lane];
        p += x[j].x * g.x + x[j].y * g.y + x[j].z * g.z + x[j].w * g.w;
    }
#pragma unroll
    for (int off = 16; off > 0; off >>= 1)
        p += __shfl_xor_sync(0xffffffffu, p, off);

    float mnew  = fmaxf(m, p);
    float scale = __expf(m - mnew);
    float w     = __expf(p - mnew);
#pragma unroll
    for (int j = 0; j < 8; j++) {
        acc[j].x = acc[j].x * scale + w * x[j].x;
        acc[j].y = acc[j].y * scale + w * x[j].y;
        acc[j].z = acc[j].z * scale + w * x[j].z;
        acc[j].w = acc[j].w * scale + w * x[j].w;
    }
    l = l * scale + w;
    m = mnew;
}

__global__ __launch_bounds__(256, 2) void pass1(const float* __restrict__ rnn,
                                                const float* __restrict__ state) {
    __shared__ float4 s_mrg[H_DIM / 4];          // 4 KB, shared merged[b,:]
    const int tid  = threadIdx.x;
    const int lane = tid & 31;
    const int wid  = tid >> 5;
    const int b     = blockIdx.x >> 4;           // all warps in CTA share b
    const int chunk = ((blockIdx.x & 15) << 3) | wid;

    {   // cooperative load of merged[b,:] into smem
        int h = tid * 4;
        int d = h >> 9;
        int hh = h & 511;
        s_mrg[tid] = *reinterpret_cast<const float4*>(
            state + (size_t)(2 + d) * B_DIM * 512 + (size_t)b * 512 + hh);
    }
    __syncthreads();

    const float* base = rnn + (size_t)(chunk * CHUNK) * (B_DIM * H_DIM)
                            + (size_t)b * H_DIM;

    float4 acc[8];
#pragma unroll
    for (int j = 0; j < 8; j++) acc[j] = make_float4(0.f, 0.f, 0.f, 0.f);
    float m = -1e30f, l = 0.f;

    float4 xa[8], xb[8];
    {   // prologue: load row 0
        const float4* r0 = reinterpret_cast<const float4*>(base);
#pragma unroll
        for (int j = 0; j < 8; j++) xa[j] = __ldcs(&r0[j * 32 + lane]);
    }

#pragma unroll 1
    for (int s = 0; s < CHUNK; s += 2) {
        // prefetch row s+1 while processing row s
        const float4* r1 = reinterpret_cast<const float4*>(
            base + (size_t)(s + 1) * (B_DIM * H_DIM));
#pragma unroll
        for (int j = 0; j < 8; j++) xb[j] = __ldcs(&r1[j * 32 + lane]);

        process_row(xa, acc, m, l, s_mrg, lane);

        // prefetch row s+2 while processing row s+1
        if (s + 2 < CHUNK) {
            const float4* r2 = reinterpret_cast<const float4*>(
                base + (size_t)(s + 2) * (B_DIM * H_DIM));
#pragma unroll
            for (int j = 0; j < 8; j++) xa[j] = __ldcs(&r2[j * 32 + lane]);
        }

        process_row(xb, acc, m, l, s_mrg, lane);
    }

    const int warp = blockIdx.x * WARPS_PER_CTA + wid;
    float4* out4 = reinterpret_cast<float4*>(g_acc + (size_t)warp * H_DIM);
#pragma unroll
    for (int j = 0; j < 8; j++) out4[j * 32 + lane] = acc[j];
    if (lane == 0) {
        g_m[warp] = m;
        g_l[warp] = l;
    }
}

// Fused combine + weighted sum. grid = (16 h-slices, 32 batches), 256 threads.
__global__ __launch_bounds__(256) void pass2(float* __restrict__ out) {
    const int slice = blockIdx.x;        // 0..15
    const int b     = blockIdx.y;        // 0..31
    const int tid   = threadIdx.x;
    const int lane  = tid & 31;
    const int wid   = tid >> 5;

    __shared__ float sw[SPLIT];
    __shared__ float s_red[8];

    // ---- compute normalized chunk weights (threads 0..127 own one chunk) ----
    float mm = -1e30f, ll = 0.f;
    if (tid < SPLIT) {
        mm = g_m[b * SPLIT + tid];
        ll = g_l[b * SPLIT + tid];
    }
    // block max over all 256 threads (upper half contributes -inf)
    float v = mm;
#pragma unroll
    for (int off = 16; off > 0; off >>= 1)
        v = fmaxf(v, __shfl_xor_sync(0xffffffffu, v, off));
    if (lane == 0) s_red[wid] = v;
    __syncthreads();
    float M = s_red[0];
#pragma unroll
    for (int k = 1; k < 8; k++) M = fmaxf(M, s_red[k]);
    __syncthreads();

    float e  = (tid < SPLIT) ? __expf(mm - M) : 0.f;
    float le = ll * e;
#pragma unroll
    for (int off = 16; off > 0; off >>= 1)
        le += __shfl_xor_sync(0xffffffffu, le, off);
    if (lane == 0) s_red[wid] = le;
    __syncthreads();
    float L = 0.f;
#pragma unroll
    for (int k = 0; k < 8; k++) L += s_red[k];
    if (tid < SPLIT) sw[tid] = e / L;
    __syncthreads();

    // ---- weighted sum over 128 chunks for 64 h values ----
    const int hq = tid & 15;             // 16 float4 = 64 floats per slice
    const int cg = tid >> 4;             // 16 groups x 8 chunks

    const float* bse = g_acc + ((size_t)b * SPLIT) * H_DIM + slice * 64 + hq * 4;

    float rx = 0.f, ry = 0.f, rz = 0.f, rw = 0.f;
#pragma unroll
    for (int k = 0; k < 8; k++) {
        int chunk = cg * 8 + k;
        float4 a = *reinterpret_cast<const float4*>(bse + (size_t)chunk * H_DIM);
        float w = sw[chunk];
        rx += w * a.x; ry += w * a.y; rz += w * a.z; rw += w * a.w;
    }

    __shared__ float4 red[256];
    red[tid] = make_float4(rx, ry, rz, rw);
    __syncthreads();
#pragma unroll
    for (int st = 8; st > 0; st >>= 1) {
        if (cg < st) {
            float4 o = red[tid + 16 * st];
            rx += o.x; ry += o.y; rz += o.z; rw += o.w;
            red[tid] = make_float4(rx, ry, rz, rw);
        }
        __syncthreads();
    }

    if (cg == 0) {
        reinterpret_cast<float4*>(out)[(b * H_DIM + slice * 64) / 4 + hq] =
            make_float4(rx, ry, rz, rw);
    }
}

extern "C" void kernel_launch(void* const* d_in, const int* in_sizes, int n_in,
                              void* d_out, int out_size) {
    const float* rnn   = (const float*)d_in[0];
    const float* state = (const float*)d_in[1];
    float* out         = (float*)d_out;

    pass1<<<NPART / WARPS_PER_CTA, 256>>>(rnn, state);
    dim3 g2(16, B_DIM);
    pass2<<<g2, 256>>>(out);
}